// round 4
// baseline (speedup 1.0000x reference)
#include <cuda_runtime.h>
#include <math.h>
#include <stdint.h>

#define NN   25000
#define NE   500000
#define NDIM 32
#define EDIM 19
#define GG   200

// ---------------- scratch (device globals) ----------------------------------
static __device__ float g_hv[NN * GG];      // hv_new (20 MB, L2-resident)
static __device__ float g_P[NN * GG];       // nf @ We1[:, :32]^T  (20 MB)
static __device__ float g_q[NN];            // hv_new . We2[0:200]
static __device__ float g_denom[NN];        // sum of exp(logit) per dst
static __device__ float g_s[NN * GG];       // sum ex*he1 per dst (20 MB)
static __device__ float g_ctx[NN * GG];

// ---------------- helpers ----------------------------------------------------
__device__ __forceinline__ float lrelu(float x) { return x > 0.f ? x : 0.01f * x; }
__device__ __forceinline__ float sigm(float x) { return 1.f / (1.f + __expf(-x)); }

__device__ __forceinline__ void redf(float* p, float v) {
    asm volatile("red.global.add.f32 [%0], %1;" :: "l"(p), "f"(v) : "memory");
}
__device__ __forceinline__ void red4(float* p, float a, float b, float c, float d) {
    asm volatile("red.global.add.v4.f32 [%0], {%1, %2, %3, %4};"
                 :: "l"(p), "f"(a), "f"(b), "f"(c), "f"(d) : "memory");
}

// scatter 25 consecutive floats starting at global offset with (grp*25)%4 = 4-HEAD misalign
template <int HEAD>
__device__ __forceinline__ void scat25(float* base, const float* v, float ex) {
#pragma unroll
    for (int j = 0; j < HEAD; j++) redf(base + j, ex * v[j]);
    constexpr int NV = (25 - HEAD) / 4;
#pragma unroll
    for (int q = 0; q < NV; q++) {
        int j = HEAD + q * 4;
        red4(base + j, ex * v[j], ex * v[j + 1], ex * v[j + 2], ex * v[j + 3]);
    }
#pragma unroll
    for (int j = HEAD + NV * 4; j < 25; j++) redf(base + j, ex * v[j]);
}

// ---------------- k_init -----------------------------------------------------
__global__ void k_init() {
    int idx = blockIdx.x * blockDim.x + threadIdx.x;
    if (idx < NN * GG) g_s[idx] = 0.f;
    if (idx < NN) g_denom[idx] = 0.f;
}

// ---------------- k_nodeproj: hv, P, q per node ------------------------------
// hv = lrelu(nf @ Wn^T + bn); P = nf @ We1[:, :32]^T; q = hv . We2[0:200]
#define NP_WNT  0                        // 32 x 228
#define NP_W1T  7296                     // 32 x 228
#define NP_INS  14592                    // 32 x 33
#define NP_BN   15648                    // 200
#define NP_W2A  15848                    // 200
#define NP_QP   16048                    // 8 x 32
#define NP_SMEM 16304

__global__ void k_nodeproj(const float* __restrict__ nf,
                           const float* __restrict__ Wn,
                           const float* __restrict__ bn,
                           const float* __restrict__ We2,
                           const float* __restrict__ We1) {
    extern __shared__ float sm[];
    float* wnt  = sm + NP_WNT;
    float* w1t  = sm + NP_W1T;
    float* ins  = sm + NP_INS;
    float* bn_s = sm + NP_BN;
    float* w2a  = sm + NP_W2A;
    float* qp   = sm + NP_QP;
    float* outh = sm;                    // staging reuse [0,6432)
    float* outp = sm + 6432;             // [6432,12864)

    int tid = threadIdx.x;
    int lane = tid & 31, grp = tid >> 5;
    int n0 = blockIdx.x * 32;

    for (int i = tid; i < GG * NDIM; i += 256) {
        int r = i >> 5, k = i & 31;
        int g = r / 25, j = r - g * 25;
        wnt[k * 228 + g * 28 + j] = Wn[i];
        w1t[k * 228 + g * 28 + j] = We1[r * 51 + k];
    }
    for (int i = tid; i < GG; i += 256) { bn_s[i] = bn[i]; w2a[i] = We2[i]; }
    for (int i = tid; i < 32 * NDIM; i += 256) {
        int n = i >> 5, k = i & 31;
        ins[k * 33 + n] = (n0 + n < NN) ? nf[(size_t)(n0 + n) * NDIM + k] : 0.f;
    }
    __syncthreads();

    float acc[28], accP[28];
#pragma unroll
    for (int j = 0; j < 28; j++) { acc[j] = (j < 25) ? bn_s[grp * 25 + j] : 0.f; accP[j] = 0.f; }

    for (int k = 0; k < NDIM; k++) {
        float x = ins[k * 33 + lane];
        const float4* wp = (const float4*)&wnt[k * 228 + grp * 28];
        const float4* pp = (const float4*)&w1t[k * 228 + grp * 28];
#pragma unroll
        for (int j4 = 0; j4 < 7; j4++) {
            float4 w = wp[j4], p = pp[j4];
            acc[j4*4+0] += x * w.x;  acc[j4*4+1] += x * w.y;
            acc[j4*4+2] += x * w.z;  acc[j4*4+3] += x * w.w;
            accP[j4*4+0] += x * p.x; accP[j4*4+1] += x * p.y;
            accP[j4*4+2] += x * p.z; accP[j4*4+3] += x * p.w;
        }
    }
    __syncthreads();                     // weights dead -> staging

    float qdot = 0.f;
#pragma unroll
    for (int j = 0; j < 25; j++) {
        float v = lrelu(acc[j]);
        outh[lane * 201 + grp * 25 + j] = v;
        outp[lane * 201 + grp * 25 + j] = accP[j];
        qdot += v * w2a[grp * 25 + j];
    }
    qp[grp * 32 + lane] = qdot;
    __syncthreads();

    for (int i = tid; i < 32 * GG; i += 256) {
        int n = i / GG, o = i - n * GG;
        if (n0 + n < NN) {
            g_hv[(size_t)(n0 + n) * GG + o] = outh[n * 201 + o];
            g_P[(size_t)(n0 + n) * GG + o]  = outp[n * 201 + o];
        }
    }
    if (tid < 32 && n0 + tid < NN) {
        float q = 0.f;
#pragma unroll
        for (int g = 0; g < 8; g++) q += qp[g * 32 + tid];
        g_q[n0 + tid] = q;
    }
}

// ---------------- k_edge1: he1 + logits + fused unnormalized scatter ---------
// NE = 500000 = 15625 exact 32-edge tiles. 256 threads, grid-stride.
#define E_W1   0                         // 19 x 228
#define E_B1   4332                      // 200
#define E_W2B  4532                      // 200
#define E_INS  4732                      // 19 x 33 = 627
#define E_PS   5360                      // 32 x 201 = 6432
#define E_PART 11792                     // 8 x 32
#define E_EXS  12048                     // 32
#define E_SD   12080                     // 64 ints
#define E_SMEM 12144
#define E_NT   (NE / 32)

__global__ void k_edge1(const float* __restrict__ ef,
                        const int* __restrict__ src,
                        const int* __restrict__ dst,
                        const float* __restrict__ We1,
                        const float* __restrict__ be1,
                        const float* __restrict__ We2,
                        const float* __restrict__ be2) {
    extern __shared__ float sm[];
    float* w1   = sm + E_W1;
    float* b1   = sm + E_B1;
    float* w2b  = sm + E_W2B;
    float* ins  = sm + E_INS;
    float* ps   = sm + E_PS;
    float* part = sm + E_PART;
    float* exs  = sm + E_EXS;
    int* src_s  = (int*)(sm + E_SD);
    int* dst_s  = src_s + 32;

    int tid = threadIdx.x;
    int lane = tid & 31, grp = tid >> 5;

    for (int i = tid; i < GG * EDIM; i += 256) {
        int r = i / EDIM, k = i - r * EDIM;
        int g = r / 25, j = r - g * 25;
        w1[k * 228 + g * 28 + j] = We1[r * 51 + NDIM + k];
    }
    for (int i = tid; i < GG; i += 256) { b1[i] = be1[i]; w2b[i] = We2[GG + i]; }
    float be2v = be2[0];
    __syncthreads();

    for (int t = blockIdx.x; t < E_NT; t += gridDim.x) {
        int e0 = t * 32;
        if (tid < 32) { src_s[tid] = src[e0 + tid]; dst_s[tid] = dst[e0 + tid]; }
        __syncthreads();

        // gather P rows (coalesced, L2-resident) and edge feats (linear)
        for (int i = tid; i < 32 * GG; i += 256) {
            int e = i / GG, f = i - e * GG;
            ps[e * 201 + f] = g_P[(size_t)src_s[e] * GG + f];
        }
        for (int i = tid; i < 32 * EDIM; i += 256) {
            int e = i / EDIM, k = i - e * EDIM;
            ins[k * 33 + e] = ef[(size_t)e0 * EDIM + i];
        }
        __syncthreads();

        float acc[28];
#pragma unroll
        for (int j = 0; j < 28; j++) acc[j] = (j < 25) ? b1[grp * 25 + j] : 0.f;

        for (int k = 0; k < EDIM; k++) {
            float x = ins[k * 33 + lane];
            const float4* wp = (const float4*)&w1[k * 228 + grp * 28];
#pragma unroll
            for (int j4 = 0; j4 < 7; j4++) {
                float4 w = wp[j4];
                acc[j4*4+0] += x * w.x; acc[j4*4+1] += x * w.y;
                acc[j4*4+2] += x * w.z; acc[j4*4+3] += x * w.w;
            }
        }

        float dotv = 0.f;
#pragma unroll
        for (int j = 0; j < 25; j++) {
            float v = lrelu(acc[j] + ps[lane * 201 + grp * 25 + j]);
            acc[j] = v;
            dotv += v * w2b[grp * 25 + j];
        }
        part[grp * 32 + lane] = dotv;
        __syncthreads();

        if (tid < 32) {
            float l = be2v + g_q[dst_s[tid]];
#pragma unroll
            for (int g = 0; g < 8; g++) l += part[g * 32 + tid];
            l = lrelu(l);
            float ex = __expf(l);        // unnormalized softmax (shift-invariant)
            exs[tid] = ex;
            atomicAdd(&g_denom[dst_s[tid]], ex);
        }
        __syncthreads();

        // scatter ex * he1 directly from registers (head/v4/tail on grp%4)
        {
            float ex = exs[lane];
            float* base = g_s + (size_t)dst_s[lane] * GG + grp * 25;
            switch (grp & 3) {
                case 0: scat25<0>(base, acc, ex); break;
                case 1: scat25<3>(base, acc, ex); break;
                case 2: scat25<2>(base, acc, ex); break;
                default: scat25<1>(base, acc, ex); break;
            }
        }
        __syncthreads();
    }
}

// ---------------- k_ctx: context = elu(Wet @ (s/denom) + bet) ----------------
#define CX_IN   0                        // 200 x 33
#define CX_W    6600                     // 50 x 228
#define CX_BET  18000                    // 200
#define CX_INV  18200                    // 32
#define CX_SMEM 18232

__global__ void k_ctx(const float* __restrict__ Wet, const float* __restrict__ bet) {
    extern __shared__ float sm[];
    float* in_s  = sm + CX_IN;
    float* w_s   = sm + CX_W;
    float* bet_s = sm + CX_BET;
    float* inv_s = sm + CX_INV;
    float* out_s = sm + CX_W;            // reuse

    int tid = threadIdx.x;
    int n0 = blockIdx.x * 32;
    int lane = tid & 31, grp = tid >> 5;

    if (tid < 32) {
        float d = (n0 + tid < NN) ? g_denom[n0 + tid] : 0.f;
        inv_s[tid] = (d > 0.f) ? (1.f / d) : 0.f;
    }
    for (int i = tid; i < GG; i += 256) bet_s[i] = bet[i];
    __syncthreads();

    for (int i = tid; i < 32 * GG; i += 256) {
        int n = i / GG, k = i - n * GG;
        float v = (n0 + n < NN) ? g_s[(size_t)(n0 + n) * GG + k] : 0.f;
        in_s[k * 33 + n] = v * inv_s[n];
    }

    float acc[28];
#pragma unroll
    for (int j = 0; j < 28; j++) acc[j] = 0.f;

    for (int c = 0; c < 4; c++) {
        __syncthreads();
        for (int i = tid; i < GG * 50; i += 256) {
            int r = i / 50, kk = i - r * 50;
            int g = r / 25, j = r - g * 25;
            w_s[kk * 228 + g * 28 + j] = Wet[(size_t)r * GG + c * 50 + kk];
        }
        __syncthreads();
        for (int kk = 0; kk < 50; kk++) {
            float x = in_s[(c * 50 + kk) * 33 + lane];
            const float4* wp = (const float4*)&w_s[kk * 228 + grp * 28];
#pragma unroll
            for (int j4 = 0; j4 < 7; j4++) {
                float4 w = wp[j4];
                acc[j4*4+0] += x * w.x; acc[j4*4+1] += x * w.y;
                acc[j4*4+2] += x * w.z; acc[j4*4+3] += x * w.w;
            }
        }
    }
    __syncthreads();
    bool has = inv_s[lane] > 0.f;
#pragma unroll
    for (int j = 0; j < 25; j++) {
        float v = acc[j] + (has ? bet_s[grp * 25 + j] : 0.f);
        out_s[lane * 201 + grp * 25 + j] = (v > 0.f) ? v : expm1f(v);
    }
    __syncthreads();
    for (int i = tid; i < 32 * GG; i += 256) {
        int n = i / GG, o = i - n * GG;
        if (n0 + n < NN) g_ctx[(size_t)(n0 + n) * GG + o] = out_s[n * 201 + o];
    }
}

// ---------------- k_gru: fully fused GRUCell + relu --------------------------
#define G_CTX  0                         // 200 x 33
#define G_HV   6600                      // 200 x 33
#define G_W    13200                     // 25 x 228 = 5700
#define G_B    18900                     // 1200
#define G_R    20100                     // 32 x 201 = 6432
#define G_SMEM 26532

__device__ __forceinline__ void gru_ldw(float* ws, const float* W, int rowbase,
                                        int cc, int tid) {
    for (int i = tid; i < GG * 25; i += 256) {
        int r = i / 25, kk = i - r * 25;
        int g = r / 25, j = r - g * 25;
        ws[kk * 228 + g * 28 + j] = W[(size_t)(rowbase + r) * GG + cc * 25 + kk];
    }
}
__device__ __forceinline__ void gru_acc(float* acc, const float* ws,
                                        const float* in_s, int cc, int lane, int grp) {
    for (int kk = 0; kk < 25; kk++) {
        float x = in_s[(cc * 25 + kk) * 33 + lane];
        const float4* wp = (const float4*)&ws[kk * 228 + grp * 28];
#pragma unroll
        for (int j4 = 0; j4 < 7; j4++) {
            float4 w = wp[j4];
            acc[j4*4+0] += x * w.x; acc[j4*4+1] += x * w.y;
            acc[j4*4+2] += x * w.z; acc[j4*4+3] += x * w.w;
        }
    }
}

__global__ void k_gru(const float* __restrict__ Wih, const float* __restrict__ bih,
                      const float* __restrict__ Whh, const float* __restrict__ bhh,
                      float* __restrict__ out) {
    extern __shared__ float sm[];
    float* ctxs = sm + G_CTX;
    float* hvs  = sm + G_HV;
    float* ws   = sm + G_W;
    float* bs   = sm + G_B;
    float* rs   = sm + G_R;

    int tid = threadIdx.x;
    int n0 = blockIdx.x * 32;
    int lane = tid & 31, grp = tid >> 5;

    for (int i = tid; i < 32 * GG; i += 256) {
        int n = i / GG, k = i - n * GG;
        bool ok = (n0 + n < NN);
        ctxs[k * 33 + n] = ok ? g_ctx[(size_t)(n0 + n) * GG + k] : 0.f;
        hvs[k * 33 + n]  = ok ? g_hv[(size_t)(n0 + n) * GG + k] : 0.f;
    }
    for (int i = tid; i < 600; i += 256) { bs[i] = bih[i]; bs[600 + i] = bhh[i]; }
    __syncthreads();   // FIX (round 3 bug): bs/ctxs/hvs must be visible before acc init

    float acc[28], acc2[28];

    // ---- Stage A: r (K=400) ----
#pragma unroll
    for (int j = 0; j < 28; j++)
        acc[j] = (j < 25) ? (bs[grp * 25 + j] + bs[600 + grp * 25 + j]) : 0.f;
    for (int c = 0; c < 16; c++) {
        const float* W  = (c < 8) ? Wih : Whh;
        const float* IN = (c < 8) ? ctxs : hvs;
        int cc = c & 7;
        __syncthreads();
        gru_ldw(ws, W, 0, cc, tid);
        __syncthreads();
        gru_acc(acc, ws, IN, cc, lane, grp);
    }
#pragma unroll
    for (int j = 0; j < 25; j++) rs[lane * 201 + grp * 25 + j] = sigm(acc[j]);

    // ---- Stage B: n ----
#pragma unroll
    for (int j = 0; j < 28; j++) {
        acc[j]  = (j < 25) ? bs[400 + grp * 25 + j]  : 0.f;   // Wih_n @ ctx
        acc2[j] = (j < 25) ? bs[1000 + grp * 25 + j] : 0.f;   // Whh_n @ hv
    }
    for (int cc = 0; cc < 8; cc++) {
        __syncthreads();
        gru_ldw(ws, Wih, 400, cc, tid);
        __syncthreads();
        gru_acc(acc, ws, ctxs, cc, lane, grp);
    }
    for (int cc = 0; cc < 8; cc++) {
        __syncthreads();
        gru_ldw(ws, Whh, 400, cc, tid);
        __syncthreads();
        gru_acc(acc2, ws, hvs, cc, lane, grp);
    }
#pragma unroll
    for (int j = 0; j < 25; j++) {
        float r = rs[lane * 201 + grp * 25 + j];
        rs[lane * 201 + grp * 25 + j] = tanhf(acc[j] + r * acc2[j]);  // same-slot overwrite
    }

    // ---- Stage C: z + combine ----
#pragma unroll
    for (int j = 0; j < 28; j++)
        acc[j] = (j < 25) ? (bs[200 + grp * 25 + j] + bs[800 + grp * 25 + j]) : 0.f;
    for (int c = 0; c < 16; c++) {
        const float* W  = (c < 8) ? Wih : Whh;
        const float* IN = (c < 8) ? ctxs : hvs;
        int cc = c & 7;
        __syncthreads();
        gru_ldw(ws, W, 200, cc, tid);
        __syncthreads();
        gru_acc(acc, ws, IN, cc, lane, grp);
    }
#pragma unroll
    for (int j = 0; j < 25; j++) {
        float z = sigm(acc[j]);
        float n = rs[lane * 201 + grp * 25 + j];
        float hv = hvs[(grp * 25 + j) * 33 + lane];
        float h = (1.f - z) * n + z * hv;
        acc[j] = fmaxf(h, 0.f);
    }
    __syncthreads();
#pragma unroll
    for (int j = 0; j < 25; j++) rs[lane * 201 + grp * 25 + j] = acc[j];
    __syncthreads();
    for (int i = tid; i < 32 * GG; i += 256) {
        int n = i / GG, o = i - n * GG;
        if (n0 + n < NN) out[(size_t)(n0 + n) * GG + o] = rs[n * 201 + o];
    }
}

// ---------------- launch -----------------------------------------------------
extern "C" void kernel_launch(void* const* d_in, const int* in_sizes, int n_in,
                              void* d_out, int out_size) {
    const float* nf  = (const float*)d_in[0];
    const float* ef  = (const float*)d_in[1];
    const int*   src = (const int*)d_in[2];
    const int*   dst = (const int*)d_in[3];
    const float* Wn  = (const float*)d_in[4];
    const float* bn  = (const float*)d_in[5];
    const float* We1 = (const float*)d_in[6];
    const float* be1 = (const float*)d_in[7];
    const float* We2 = (const float*)d_in[8];
    const float* be2 = (const float*)d_in[9];
    const float* Wet = (const float*)d_in[10];
    const float* bet = (const float*)d_in[11];
    const float* Wih = (const float*)d_in[12];
    const float* bih = (const float*)d_in[13];
    const float* Whh = (const float*)d_in[14];
    const float* bhh = (const float*)d_in[15];
    float* out = (float*)d_out;

    cudaFuncSetAttribute(k_nodeproj, cudaFuncAttributeMaxDynamicSharedMemorySize, NP_SMEM * 4);
    cudaFuncSetAttribute(k_edge1,    cudaFuncAttributeMaxDynamicSharedMemorySize, E_SMEM * 4);
    cudaFuncSetAttribute(k_ctx,      cudaFuncAttributeMaxDynamicSharedMemorySize, CX_SMEM * 4);
    cudaFuncSetAttribute(k_gru,      cudaFuncAttributeMaxDynamicSharedMemorySize, G_SMEM * 4);

    k_init<<<(NN * GG + 255) / 256, 256>>>();
    k_nodeproj<<<(NN + 31) / 32, 256, NP_SMEM * 4>>>(nf, Wn, bn, We2, We1);
    k_edge1<<<1184, 256, E_SMEM * 4>>>(ef, src, dst, We1, be1, We2, be2);
    k_ctx<<<(NN + 31) / 32, 256, CX_SMEM * 4>>>(Wet, bet);
    k_gru<<<(NN + 31) / 32, 256, G_SMEM * 4>>>(Wih, bih, Whh, bhh, out);
}

// round 5
// speedup vs baseline: 1.5160x; 1.5160x over previous
#include <cuda_runtime.h>
#include <math.h>
#include <stdint.h>

#define NN   25000
#define NE   500000
#define NDIM 32
#define EDIM 19
#define GG   200

// ---------------- scratch (device globals) ----------------------------------
static __device__ float g_hv[NN * GG];      // hv_new (20 MB, L2-resident)
static __device__ float g_P[NN * GG];       // nf @ We1[:, :32]^T  (20 MB)
static __device__ float g_q[NN];            // hv_new . We2[0:200]
static __device__ float g_denom[NN];        // sum of exp(logit) per dst
static __device__ float g_inv[NN];          // 1/denom (0 if no edges)
static __device__ float g_s[NN * GG];       // sum ex*he1 per dst (20 MB)
static __device__ float g_ctx[NN * GG];
static __device__ float g_gates[(size_t)6 * NN * GG];  // ir iz in hr hz hn

// ---------------- helpers ----------------------------------------------------
__device__ __forceinline__ float lrelu(float x) { return x > 0.f ? x : 0.01f * x; }
__device__ __forceinline__ float sigm(float x) { return 1.f / (1.f + __expf(-x)); }

__device__ __forceinline__ void redf(float* p, float v) {
    asm volatile("red.global.add.f32 [%0], %1;" :: "l"(p), "f"(v) : "memory");
}
__device__ __forceinline__ void red4(float* p, float a, float b, float c, float d) {
    asm volatile("red.global.add.v4.f32 [%0], {%1, %2, %3, %4};"
                 :: "l"(p), "f"(a), "f"(b), "f"(c), "f"(d) : "memory");
}

template <int HEAD>
__device__ __forceinline__ void scat25(float* base, const float* v, float ex) {
#pragma unroll
    for (int j = 0; j < HEAD; j++) redf(base + j, ex * v[j]);
    constexpr int NV = (25 - HEAD) / 4;
#pragma unroll
    for (int q = 0; q < NV; q++) {
        int j = HEAD + q * 4;
        red4(base + j, ex * v[j], ex * v[j + 1], ex * v[j + 2], ex * v[j + 3]);
    }
#pragma unroll
    for (int j = HEAD + NV * 4; j < 25; j++) redf(base + j, ex * v[j]);
}

// ---------------- k_init -----------------------------------------------------
__global__ void k_init() {
    int idx = blockIdx.x * blockDim.x + threadIdx.x;
    if (idx < NN * GG) g_s[idx] = 0.f;
    if (idx < NN) g_denom[idx] = 0.f;
}

// ---------------- k_inv ------------------------------------------------------
__global__ void k_inv() {
    int idx = blockIdx.x * blockDim.x + threadIdx.x;
    if (idx < NN) {
        float d = g_denom[idx];
        g_inv[idx] = (d > 0.f) ? (1.f / d) : 0.f;
    }
}

// ---------------- k_nodeproj: hv, P, q per node ------------------------------
#define NP_WNT  0                        // 32 x 228
#define NP_W1T  7296                     // 32 x 228
#define NP_INS  14592                    // 32 x 33
#define NP_BN   15648                    // 200
#define NP_W2A  15848                    // 200
#define NP_QP   16048                    // 8 x 32
#define NP_SMEM 16304

__global__ void k_nodeproj(const float* __restrict__ nf,
                           const float* __restrict__ Wn,
                           const float* __restrict__ bn,
                           const float* __restrict__ We2,
                           const float* __restrict__ We1) {
    extern __shared__ float sm[];
    float* wnt  = sm + NP_WNT;
    float* w1t  = sm + NP_W1T;
    float* ins  = sm + NP_INS;
    float* bn_s = sm + NP_BN;
    float* w2a  = sm + NP_W2A;
    float* qp   = sm + NP_QP;
    float* outh = sm;                    // staging reuse [0,6432)
    float* outp = sm + 6432;             // [6432,12864)

    int tid = threadIdx.x;
    int lane = tid & 31, grp = tid >> 5;
    int n0 = blockIdx.x * 32;

    for (int i = tid; i < GG * NDIM; i += 256) {
        int r = i >> 5, k = i & 31;
        int g = r / 25, j = r - g * 25;
        wnt[k * 228 + g * 28 + j] = Wn[i];
        w1t[k * 228 + g * 28 + j] = We1[r * 51 + k];
    }
    for (int i = tid; i < GG; i += 256) { bn_s[i] = bn[i]; w2a[i] = We2[i]; }
    for (int i = tid; i < 32 * NDIM; i += 256) {
        int n = i >> 5, k = i & 31;
        ins[k * 33 + n] = (n0 + n < NN) ? nf[(size_t)(n0 + n) * NDIM + k] : 0.f;
    }
    __syncthreads();

    float acc[28], accP[28];
#pragma unroll
    for (int j = 0; j < 28; j++) { acc[j] = (j < 25) ? bn_s[grp * 25 + j] : 0.f; accP[j] = 0.f; }

    for (int k = 0; k < NDIM; k++) {
        float x = ins[k * 33 + lane];
        const float4* wp = (const float4*)&wnt[k * 228 + grp * 28];
        const float4* pp = (const float4*)&w1t[k * 228 + grp * 28];
#pragma unroll
        for (int j4 = 0; j4 < 7; j4++) {
            float4 w = wp[j4], p = pp[j4];
            acc[j4*4+0] += x * w.x;  acc[j4*4+1] += x * w.y;
            acc[j4*4+2] += x * w.z;  acc[j4*4+3] += x * w.w;
            accP[j4*4+0] += x * p.x; accP[j4*4+1] += x * p.y;
            accP[j4*4+2] += x * p.z; accP[j4*4+3] += x * p.w;
        }
    }
    __syncthreads();

    float qdot = 0.f;
#pragma unroll
    for (int j = 0; j < 25; j++) {
        float v = lrelu(acc[j]);
        outh[lane * 201 + grp * 25 + j] = v;
        outp[lane * 201 + grp * 25 + j] = accP[j];
        qdot += v * w2a[grp * 25 + j];
    }
    qp[grp * 32 + lane] = qdot;
    __syncthreads();

    for (int i = tid; i < 32 * GG; i += 256) {
        int n = i / GG, o = i - n * GG;
        if (n0 + n < NN) {
            g_hv[(size_t)(n0 + n) * GG + o] = outh[n * 201 + o];
            g_P[(size_t)(n0 + n) * GG + o]  = outp[n * 201 + o];
        }
    }
    if (tid < 32 && n0 + tid < NN) {
        float q = 0.f;
#pragma unroll
        for (int g = 0; g < 8; g++) q += qp[g * 32 + tid];
        g_q[n0 + tid] = q;
    }
}

// ---------------- k_edge1: he1 + logits + fused unnormalized scatter ---------
#define E_W1   0                         // 19 x 228
#define E_B1   4332
#define E_W2B  4532
#define E_INS  4732                      // 19 x 33
#define E_PS   5360                      // 32 x 201
#define E_PART 11792                     // 8 x 32
#define E_EXS  12048                     // 32
#define E_SD   12080                     // 64 ints
#define E_SMEM 12144
#define E_NT   (NE / 32)

__global__ void k_edge1(const float* __restrict__ ef,
                        const int* __restrict__ src,
                        const int* __restrict__ dst,
                        const float* __restrict__ We1,
                        const float* __restrict__ be1,
                        const float* __restrict__ We2,
                        const float* __restrict__ be2) {
    extern __shared__ float sm[];
    float* w1   = sm + E_W1;
    float* b1   = sm + E_B1;
    float* w2b  = sm + E_W2B;
    float* ins  = sm + E_INS;
    float* ps   = sm + E_PS;
    float* part = sm + E_PART;
    float* exs  = sm + E_EXS;
    int* src_s  = (int*)(sm + E_SD);
    int* dst_s  = src_s + 32;

    int tid = threadIdx.x;
    int lane = tid & 31, grp = tid >> 5;

    for (int i = tid; i < GG * EDIM; i += 256) {
        int r = i / EDIM, k = i - r * EDIM;
        int g = r / 25, j = r - g * 25;
        w1[k * 228 + g * 28 + j] = We1[r * 51 + NDIM + k];
    }
    for (int i = tid; i < GG; i += 256) { b1[i] = be1[i]; w2b[i] = We2[GG + i]; }
    float be2v = be2[0];
    __syncthreads();

    for (int t = blockIdx.x; t < E_NT; t += gridDim.x) {
        int e0 = t * 32;
        if (tid < 32) { src_s[tid] = src[e0 + tid]; dst_s[tid] = dst[e0 + tid]; }
        __syncthreads();

        for (int i = tid; i < 32 * GG; i += 256) {
            int e = i / GG, f = i - e * GG;
            ps[e * 201 + f] = g_P[(size_t)src_s[e] * GG + f];
        }
        for (int i = tid; i < 32 * EDIM; i += 256) {
            int e = i / EDIM, k = i - e * EDIM;
            ins[k * 33 + e] = ef[(size_t)e0 * EDIM + i];
        }
        __syncthreads();

        float acc[28];
#pragma unroll
        for (int j = 0; j < 28; j++) acc[j] = (j < 25) ? b1[grp * 25 + j] : 0.f;

        for (int k = 0; k < EDIM; k++) {
            float x = ins[k * 33 + lane];
            const float4* wp = (const float4*)&w1[k * 228 + grp * 28];
#pragma unroll
            for (int j4 = 0; j4 < 7; j4++) {
                float4 w = wp[j4];
                acc[j4*4+0] += x * w.x; acc[j4*4+1] += x * w.y;
                acc[j4*4+2] += x * w.z; acc[j4*4+3] += x * w.w;
            }
        }

        float dotv = 0.f;
#pragma unroll
        for (int j = 0; j < 25; j++) {
            float v = lrelu(acc[j] + ps[lane * 201 + grp * 25 + j]);
            acc[j] = v;
            dotv += v * w2b[grp * 25 + j];
        }
        part[grp * 32 + lane] = dotv;
        __syncthreads();

        if (tid < 32) {
            float l = be2v + g_q[dst_s[tid]];
#pragma unroll
            for (int g = 0; g < 8; g++) l += part[g * 32 + tid];
            l = lrelu(l);
            float ex = __expf(l);
            exs[tid] = ex;
            atomicAdd(&g_denom[dst_s[tid]], ex);
        }
        __syncthreads();

        {
            float ex = exs[lane];
            float* base = g_s + (size_t)dst_s[lane] * GG + grp * 25;
            switch (grp & 3) {
                case 0: scat25<0>(base, acc, ex); break;
                case 1: scat25<3>(base, acc, ex); break;
                case 2: scat25<2>(base, acc, ex); break;
                default: scat25<1>(base, acc, ex); break;
            }
        }
        __syncthreads();
    }
}

// ---------------- k_gemm200: weights-resident 200x200 GEMM -------------------
// 512 threads, 64-node tiles, grid-stride over 391 tiles. One block = one
// weight slice held in smem for the whole kernel; only activations stream.
// MODE 0: ctx = elu(Wet @ (s*inv) + has*bet)   (grid.y = 1)
// MODE 1: gates slice y: (y<3 ? Wih : Whh) gate y%3 on (y<3 ? ctx : hv) + bias
#define GM_W    0                        // 200 x 208 = 41600
#define GM_IN   41600                    // 200 x 65 = 13000 (reused as out 64x201)
#define GM_B    54600                    // 208
#define GM_SMEM 54816                    // 219,264 bytes
#define GM_TILES ((NN + 63) / 64)        // 391

template <int MODE>
__global__ void __launch_bounds__(512, 1)
k_gemm200(const float* __restrict__ Wp, const float* __restrict__ Wp2,
          const float* __restrict__ bp, const float* __restrict__ bp2) {
    extern __shared__ float sm[];
    float* w_s  = sm + GM_W;
    float* in_s = sm + GM_IN;
    float* b_s  = sm + GM_B;
    float* out_s = sm + GM_IN;           // alias (sync-guarded)

    int tid = threadIdx.x;
    int lane = tid & 63;                 // node within tile
    int grp = tid >> 6;                  // 0..7 -> 25 outputs

    const float* A; const float* W; const float* b; float* out;
    if (MODE == 0) {
        A = g_s; W = Wp; b = bp; out = g_ctx;
    } else {
        int y = blockIdx.y;
        A = (y < 3) ? g_ctx : g_hv;
        W = ((y < 3) ? Wp : Wp2) + (size_t)(y % 3) * GG * GG;
        b = ((y < 3) ? bp : bp2) + (y % 3) * GG;
        out = g_gates + (size_t)y * NN * GG;
    }

    // load weight slice once (transposed, float2-aligned groups of 26)
    for (int i = tid; i < GG * GG; i += 512) {
        int r = i / GG, k = i - r * GG;
        int g = r / 25, j = r - g * 25;
        w_s[k * 208 + g * 26 + j] = W[i];
    }
    for (int i = tid; i < GG; i += 512) b_s[i] = b[i];

    for (int t = blockIdx.x; t < GM_TILES; t += gridDim.x) {
        int n0 = t * 64;
        __syncthreads();                 // prev out_s reads done / weights ready

        for (int i = tid; i < 64 * GG; i += 512) {
            int n = i / GG, k = i - n * GG;
            int gn = n0 + n;
            float v = 0.f;
            if (gn < NN) {
                v = A[(size_t)gn * GG + k];
                if (MODE == 0) v *= g_inv[gn];
            }
            in_s[k * 65 + n] = v;
        }
        __syncthreads();

        float acc[25];
#pragma unroll
        for (int j = 0; j < 25; j++) acc[j] = (MODE == 0) ? 0.f : b_s[grp * 25 + j];

#pragma unroll 2
        for (int k = 0; k < GG; k++) {
            float x = in_s[k * 65 + lane];
            const float2* wp = (const float2*)&w_s[k * 208 + grp * 26];
#pragma unroll
            for (int j2 = 0; j2 < 12; j2++) {
                float2 w = wp[j2];
                acc[j2 * 2 + 0] += x * w.x;
                acc[j2 * 2 + 1] += x * w.y;
            }
            acc[24] += x * w_s[k * 208 + grp * 26 + 24];
        }
        __syncthreads();                 // in_s reads done -> out_s writes OK

        if (MODE == 0) {
            int gn = n0 + lane;
            float has = (gn < NN && g_inv[gn] > 0.f) ? 1.f : 0.f;
#pragma unroll
            for (int j = 0; j < 25; j++) {
                float v = acc[j] + has * b_s[grp * 25 + j];
                out_s[lane * 201 + grp * 25 + j] = (v > 0.f) ? v : expm1f(v);
            }
        } else {
#pragma unroll
            for (int j = 0; j < 25; j++)
                out_s[lane * 201 + grp * 25 + j] = acc[j];
        }
        __syncthreads();

        for (int i = tid; i < 64 * GG; i += 512) {
            int n = i / GG, o = i - n * GG;
            if (n0 + n < NN) out[(size_t)(n0 + n) * GG + o] = out_s[n * 201 + o];
        }
    }
}

// ---------------- k_gate: elementwise GRU combine + relu ---------------------
__global__ void k_gate(float* __restrict__ out) {
    int idx = blockIdx.x * blockDim.x + threadIdx.x;
    if (idx >= NN * GG) return;
    const size_t S = (size_t)NN * GG;
    float ir = g_gates[idx],         iz = g_gates[S + idx],     inn = g_gates[2 * S + idx];
    float hr = g_gates[3 * S + idx], hz = g_gates[4 * S + idx], hn  = g_gates[5 * S + idx];
    float r = sigm(ir + hr);
    float z = sigm(iz + hz);
    float n = tanhf(inn + r * hn);
    float hv = g_hv[idx];
    float h = (1.f - z) * n + z * hv;
    out[idx] = fmaxf(h, 0.f);
}

// ---------------- launch -----------------------------------------------------
extern "C" void kernel_launch(void* const* d_in, const int* in_sizes, int n_in,
                              void* d_out, int out_size) {
    const float* nf  = (const float*)d_in[0];
    const float* ef  = (const float*)d_in[1];
    const int*   src = (const int*)d_in[2];
    const int*   dst = (const int*)d_in[3];
    const float* Wn  = (const float*)d_in[4];
    const float* bn  = (const float*)d_in[5];
    const float* We1 = (const float*)d_in[6];
    const float* be1 = (const float*)d_in[7];
    const float* We2 = (const float*)d_in[8];
    const float* be2 = (const float*)d_in[9];
    const float* Wet = (const float*)d_in[10];
    const float* bet = (const float*)d_in[11];
    const float* Wih = (const float*)d_in[12];
    const float* bih = (const float*)d_in[13];
    const float* Whh = (const float*)d_in[14];
    const float* bhh = (const float*)d_in[15];
    float* out = (float*)d_out;

    cudaFuncSetAttribute(k_nodeproj, cudaFuncAttributeMaxDynamicSharedMemorySize, NP_SMEM * 4);
    cudaFuncSetAttribute(k_edge1,    cudaFuncAttributeMaxDynamicSharedMemorySize, E_SMEM * 4);
    cudaFuncSetAttribute(k_gemm200<0>, cudaFuncAttributeMaxDynamicSharedMemorySize, GM_SMEM * 4);
    cudaFuncSetAttribute(k_gemm200<1>, cudaFuncAttributeMaxDynamicSharedMemorySize, GM_SMEM * 4);

    k_init<<<(NN * GG + 255) / 256, 256>>>();
    k_nodeproj<<<(NN + 31) / 32, 256, NP_SMEM * 4>>>(nf, Wn, bn, We2, We1);
    k_edge1<<<1184, 256, E_SMEM * 4>>>(ef, src, dst, We1, be1, We2, be2);
    k_inv<<<(NN + 255) / 256, 256>>>();
    k_gemm200<0><<<dim3(130, 1), 512, GM_SMEM * 4>>>(Wet, nullptr, bet, nullptr);
    k_gemm200<1><<<dim3(130, 6), 512, GM_SMEM * 4>>>(Wih, Whh, bih, bhh);
    k_gate<<<(NN * GG + 255) / 256, 256>>>(out);
}

// round 9
// speedup vs baseline: 1.8846x; 1.2431x over previous
#include <cuda_runtime.h>
#include <cuda_bf16.h>
#include <mma.h>
#include <math.h>
#include <stdint.h>

using namespace nvcuda;

#define NN   25000
#define NE   500000
#define NDIM 32
#define EDIM 19
#define GG   200

// ---- tensor-GEMM geometry ---------------------------------------------------
#define NTILE 196                 // M-tiles of 128 nodes
#define MPAD  (NTILE * 128)       // 25088
#define KP    208                 // K padded to 13 x 16
#define KT    13                  // k-steps
#define NT    13                  // output 16-col tiles (208)
#define APL   (128 * 24)          // smem A plane (elements)
#define BPL   (208 * 24)          // smem B plane (elements)
#define AGPL  ((size_t)MPAD * KP) // global A plane (elements)
#define WPL   ((size_t)KP * KP)   // global W plane per slice (elements)

// ---------------- scratch (device globals) ----------------------------------
static __device__ float g_hv[NN * GG];
static __device__ float g_P[NN * GG];
static __device__ float g_q[NN];
static __device__ float g_denom[NN];
static __device__ float g_inv[NN];
static __device__ float g_s[NN * GG];
static __device__ float g_gates[(size_t)6 * NN * GG];
static __device__ __align__(128) __nv_bfloat16 g_Wpk[7 * 2 * KP * KP];     // [s][hilo][n][k]
static __device__ __align__(128) __nv_bfloat16 g_Ahv[2 * (size_t)MPAD * KP];
static __device__ __align__(128) __nv_bfloat16 g_As[2 * (size_t)MPAD * KP];
static __device__ __align__(128) __nv_bfloat16 g_Actx[2 * (size_t)MPAD * KP];

// ---------------- helpers ----------------------------------------------------
__device__ __forceinline__ float lrelu(float x) { return x > 0.f ? x : 0.01f * x; }
__device__ __forceinline__ float sigm(float x) { return 1.f / (1.f + __expf(-x)); }
__device__ __forceinline__ void bfsplit(float x, __nv_bfloat16& hi, __nv_bfloat16& lo) {
    hi = __float2bfloat16(x);
    lo = __float2bfloat16(x - __bfloat162float(hi));
}

__device__ __forceinline__ void redf(float* p, float v) {
    asm volatile("red.global.add.f32 [%0], %1;" :: "l"(p), "f"(v) : "memory");
}
__device__ __forceinline__ void red4(float* p, float a, float b, float c, float d) {
    asm volatile("red.global.add.v4.f32 [%0], {%1, %2, %3, %4};"
                 :: "l"(p), "f"(a), "f"(b), "f"(c), "f"(d) : "memory");
}

template <int HEAD>
__device__ __forceinline__ void scat25(float* base, const float* v, float ex) {
#pragma unroll
    for (int j = 0; j < HEAD; j++) redf(base + j, ex * v[j]);
    constexpr int NV = (25 - HEAD) / 4;
#pragma unroll
    for (int q = 0; q < NV; q++) {
        int j = HEAD + q * 4;
        red4(base + j, ex * v[j], ex * v[j + 1], ex * v[j + 2], ex * v[j + 3]);
    }
#pragma unroll
    for (int j = HEAD + NV * 4; j < 25; j++) redf(base + j, ex * v[j]);
}

// ---------------- k_init -----------------------------------------------------
__global__ void k_init() {
    int idx = blockIdx.x * blockDim.x + threadIdx.x;
    if (idx < NN * GG) g_s[idx] = 0.f;
    if (idx < NN) g_denom[idx] = 0.f;
}

// ---------------- k_inv ------------------------------------------------------
__global__ void k_inv() {
    int idx = blockIdx.x * blockDim.x + threadIdx.x;
    if (idx < NN) {
        float d = g_denom[idx];
        g_inv[idx] = (d > 0.f) ? (1.f / d) : 0.f;
    }
}

// ---------------- k_packW: weights -> bf16 hi/lo row-major --------------------
// slice 0 = Wet, 1..3 = Wih gates r/z/n, 4..6 = Whh gates r/z/n
__global__ void k_packW(const float* __restrict__ Wet,
                        const float* __restrict__ Wih,
                        const float* __restrict__ Whh) {
    int idx = blockIdx.x * 256 + threadIdx.x;
    if (idx >= 7 * KP * KP) return;
    int s = idx / (KP * KP);
    int rem = idx - s * (KP * KP);
    int n = rem / KP, k = rem - n * KP;
    float v = 0.f;
    if (n < GG && k < GG) {
        if (s == 0)       v = Wet[n * GG + k];
        else if (s < 4)   v = Wih[(size_t)((s - 1) * GG + n) * GG + k];
        else              v = Whh[(size_t)((s - 4) * GG + n) * GG + k];
    }
    __nv_bfloat16 hi, lo; bfsplit(v, hi, lo);
    g_Wpk[(size_t)(s * 2) * KP * KP + rem] = hi;
    g_Wpk[(size_t)(s * 2 + 1) * KP * KP + rem] = lo;
}

// ---------------- k_packS: (s * inv) -> bf16 hi/lo planes ---------------------
__global__ void k_packS() {
    size_t idx = (size_t)blockIdx.x * 256 + threadIdx.x;
    if (idx >= (size_t)MPAD * KP) return;
    int node = (int)(idx / KP), k = (int)(idx - (size_t)node * KP);
    float v = 0.f;
    if (node < NN && k < GG) v = g_s[(size_t)node * GG + k] * g_inv[node];
    __nv_bfloat16 hi, lo; bfsplit(v, hi, lo);
    g_As[idx] = hi;
    g_As[AGPL + idx] = lo;
}

// ---------------- k_nodeproj: hv, P, q per node + hv bf16 planes --------------
#define NP_WNT  0
#define NP_W1T  7296
#define NP_INS  14592
#define NP_BN   15648
#define NP_W2A  15848
#define NP_QP   16048
#define NP_SMEM 16304

__global__ void k_nodeproj(const float* __restrict__ nf,
                           const float* __restrict__ Wn,
                           const float* __restrict__ bn,
                           const float* __restrict__ We2,
                           const float* __restrict__ We1) {
    extern __shared__ float sm[];
    float* wnt  = sm + NP_WNT;
    float* w1t  = sm + NP_W1T;
    float* ins  = sm + NP_INS;
    float* bn_s = sm + NP_BN;
    float* w2a  = sm + NP_W2A;
    float* qp   = sm + NP_QP;
    float* outh = sm;
    float* outp = sm + 6432;

    int tid = threadIdx.x;
    int lane = tid & 31, grp = tid >> 5;
    int n0 = blockIdx.x * 32;

    for (int i = tid; i < GG * NDIM; i += 256) {
        int r = i >> 5, k = i & 31;
        int g = r / 25, j = r - g * 25;
        wnt[k * 228 + g * 28 + j] = Wn[i];
        w1t[k * 228 + g * 28 + j] = We1[r * 51 + k];
    }
    for (int i = tid; i < GG; i += 256) { bn_s[i] = bn[i]; w2a[i] = We2[i]; }
    for (int i = tid; i < 32 * NDIM; i += 256) {
        int n = i >> 5, k = i & 31;
        ins[k * 33 + n] = (n0 + n < NN) ? nf[(size_t)(n0 + n) * NDIM + k] : 0.f;
    }
    __syncthreads();

    float acc[28], accP[28];
#pragma unroll
    for (int j = 0; j < 28; j++) { acc[j] = (j < 25) ? bn_s[grp * 25 + j] : 0.f; accP[j] = 0.f; }

    for (int k = 0; k < NDIM; k++) {
        float x = ins[k * 33 + lane];
        const float4* wp = (const float4*)&wnt[k * 228 + grp * 28];
        const float4* pp = (const float4*)&w1t[k * 228 + grp * 28];
#pragma unroll
        for (int j4 = 0; j4 < 7; j4++) {
            float4 w = wp[j4], p = pp[j4];
            acc[j4*4+0] += x * w.x;  acc[j4*4+1] += x * w.y;
            acc[j4*4+2] += x * w.z;  acc[j4*4+3] += x * w.w;
            accP[j4*4+0] += x * p.x; accP[j4*4+1] += x * p.y;
            accP[j4*4+2] += x * p.z; accP[j4*4+3] += x * p.w;
        }
    }
    __syncthreads();

    float qdot = 0.f;
#pragma unroll
    for (int j = 0; j < 25; j++) {
        float v = lrelu(acc[j]);
        outh[lane * 201 + grp * 25 + j] = v;
        outp[lane * 201 + grp * 25 + j] = accP[j];
        qdot += v * w2a[grp * 25 + j];
    }
    qp[grp * 32 + lane] = qdot;
    __syncthreads();

    for (int i = tid; i < 32 * GG; i += 256) {
        int n = i / GG, o = i - n * GG;
        if (n0 + n < NN) {
            g_hv[(size_t)(n0 + n) * GG + o] = outh[n * 201 + o];
            g_P[(size_t)(n0 + n) * GG + o]  = outp[n * 201 + o];
        }
    }
    // hv bf16 hi/lo row-major planes (zero-padded K and pad nodes)
    for (int i = tid; i < 32 * KP; i += 256) {
        int n = i / KP, k = i - n * KP;
        int node = n0 + n;
        float v = (k < GG && node < NN) ? outh[n * 201 + k] : 0.f;
        __nv_bfloat16 hi, lo; bfsplit(v, hi, lo);
        size_t off = (size_t)node * KP + k;
        g_Ahv[off] = hi;
        g_Ahv[AGPL + off] = lo;
    }
    if (tid < 32 && n0 + tid < NN) {
        float q = 0.f;
#pragma unroll
        for (int g = 0; g < 8; g++) q += qp[g * 32 + tid];
        g_q[n0 + tid] = q;
    }
}

// ---------------- k_edge1 (unchanged from round 5) ----------------------------
#define E_W1   0
#define E_B1   4332
#define E_W2B  4532
#define E_INS  4732
#define E_PS   5360
#define E_PART 11792
#define E_EXS  12048
#define E_SD   12080
#define E_SMEM 12144
#define E_NT   (NE / 32)

__global__ void k_edge1(const float* __restrict__ ef,
                        const int* __restrict__ src,
                        const int* __restrict__ dst,
                        const float* __restrict__ We1,
                        const float* __restrict__ be1,
                        const float* __restrict__ We2,
                        const float* __restrict__ be2) {
    extern __shared__ float sm[];
    float* w1   = sm + E_W1;
    float* b1   = sm + E_B1;
    float* w2b  = sm + E_W2B;
    float* ins  = sm + E_INS;
    float* ps   = sm + E_PS;
    float* part = sm + E_PART;
    float* exs  = sm + E_EXS;
    int* src_s  = (int*)(sm + E_SD);
    int* dst_s  = src_s + 32;

    int tid = threadIdx.x;
    int lane = tid & 31, grp = tid >> 5;

    for (int i = tid; i < GG * EDIM; i += 256) {
        int r = i / EDIM, k = i - r * EDIM;
        int g = r / 25, j = r - g * 25;
        w1[k * 228 + g * 28 + j] = We1[r * 51 + NDIM + k];
    }
    for (int i = tid; i < GG; i += 256) { b1[i] = be1[i]; w2b[i] = We2[GG + i]; }
    float be2v = be2[0];
    __syncthreads();

    for (int t = blockIdx.x; t < E_NT; t += gridDim.x) {
        int e0 = t * 32;
        if (tid < 32) { src_s[tid] = src[e0 + tid]; dst_s[tid] = dst[e0 + tid]; }
        __syncthreads();

        for (int i = tid; i < 32 * GG; i += 256) {
            int e = i / GG, f = i - e * GG;
            ps[e * 201 + f] = g_P[(size_t)src_s[e] * GG + f];
        }
        for (int i = tid; i < 32 * EDIM; i += 256) {
            int e = i / EDIM, k = i - e * EDIM;
            ins[k * 33 + e] = ef[(size_t)e0 * EDIM + i];
        }
        __syncthreads();

        float acc[28];
#pragma unroll
        for (int j = 0; j < 28; j++) acc[j] = (j < 25) ? b1[grp * 25 + j] : 0.f;

        for (int k = 0; k < EDIM; k++) {
            float x = ins[k * 33 + lane];
            const float4* wp = (const float4*)&w1[k * 228 + grp * 28];
#pragma unroll
            for (int j4 = 0; j4 < 7; j4++) {
                float4 w = wp[j4];
                acc[j4*4+0] += x * w.x; acc[j4*4+1] += x * w.y;
                acc[j4*4+2] += x * w.z; acc[j4*4+3] += x * w.w;
            }
        }

        float dotv = 0.f;
#pragma unroll
        for (int j = 0; j < 25; j++) {
            float v = lrelu(acc[j] + ps[lane * 201 + grp * 25 + j]);
            acc[j] = v;
            dotv += v * w2b[grp * 25 + j];
        }
        part[grp * 32 + lane] = dotv;
        __syncthreads();

        if (tid < 32) {
            float l = be2v + g_q[dst_s[tid]];
#pragma unroll
            for (int g = 0; g < 8; g++) l += part[g * 32 + tid];
            l = lrelu(l);
            float ex = __expf(l);
            exs[tid] = ex;
            atomicAdd(&g_denom[dst_s[tid]], ex);
        }
        __syncthreads();

        {
            float ex = exs[lane];
            float* base = g_s + (size_t)dst_s[lane] * GG + grp * 25;
            switch (grp & 3) {
                case 0: scat25<0>(base, acc, ex); break;
                case 1: scat25<3>(base, acc, ex); break;
                case 2: scat25<2>(base, acc, ex); break;
                default: scat25<1>(base, acc, ex); break;
            }
        }
        __syncthreads();
    }
}

// ---------------- k_wmma: bf16-split tensor GEMM (M=128/block) ----------------
// MODE 0: ctx = elu(Wet @ (s*inv) + has*bet) -> g_Actx planes   (grid 196)
// MODE 1: gate slice y -> g_gates[y] fp32                       (grid 196 x 6)
// smem: As 2x128x24 bf16 | Bs 2x208x24 bf16 | patch 8x16x20 f32 | bias 208 f32
#define WM_SMEM (12288 + 19968 + 10240 + 832)

template <int MODE>
__global__ void __launch_bounds__(256)
k_wmma(const float* __restrict__ bias_a, const float* __restrict__ bias_b) {
    __shared__ __align__(16) unsigned char smraw[WM_SMEM];
    __nv_bfloat16* As = (__nv_bfloat16*)smraw;                       // [2][128][24]
    __nv_bfloat16* Bs = (__nv_bfloat16*)(smraw + 12288);             // [2][208][24]
    float* patch  = (float*)(smraw + 12288 + 19968);                 // [8][16][20]
    float* bias_s = (float*)(smraw + 12288 + 19968 + 10240);         // [208]

    int tid = threadIdx.x, lane = tid & 31, warp = tid >> 5;
    int tile = blockIdx.x;
    int y = (MODE == 0) ? 0 : blockIdx.y;

    const __nv_bfloat16* Ag = (MODE == 0) ? g_As : ((y < 3) ? g_Actx : g_Ahv);
    const __nv_bfloat16* Wh = g_Wpk + (size_t)(((MODE == 0) ? 0 : (1 + y)) * 2) * KP * KP;
    const float* bias = (MODE == 0) ? bias_a
                        : ((y < 3) ? (bias_a + y * GG) : (bias_b + (y - 3) * GG));

    for (int i = tid; i < KP; i += 256) bias_s[i] = (i < GG) ? bias[i] : 0.f;

    wmma::fragment<wmma::accumulator, 16, 16, 16, float> acc[NT];
#pragma unroll
    for (int nt = 0; nt < NT; nt++) wmma::fill_fragment(acc[nt], 0.f);

    for (int kt = 0; kt < KT; kt++) {
        __syncthreads();
        for (int i = tid; i < 128 * 16; i += 256) {
            int r = i >> 4, k = i & 15;
            size_t go = (size_t)(tile * 128 + r) * KP + kt * 16 + k;
            As[r * 24 + k] = Ag[go];
            As[APL + r * 24 + k] = Ag[AGPL + go];
        }
        for (int i = tid; i < 208 * 16; i += 256) {
            int n = i >> 4, k = i & 15;
            size_t go = (size_t)n * KP + kt * 16 + k;
            Bs[n * 24 + k] = Wh[go];
            Bs[BPL + n * 24 + k] = Wh[WPL + go];
        }
        __syncthreads();

        wmma::fragment<wmma::matrix_a, 16, 16, 16, __nv_bfloat16, wmma::row_major> a_hi, a_lo;
        wmma::load_matrix_sync(a_hi, As + warp * 16 * 24, 24);
        wmma::load_matrix_sync(a_lo, As + APL + warp * 16 * 24, 24);
#pragma unroll
        for (int nt = 0; nt < NT; nt++) {
            wmma::fragment<wmma::matrix_b, 16, 16, 16, __nv_bfloat16, wmma::col_major> b_hi, b_lo;
            wmma::load_matrix_sync(b_hi, Bs + nt * 16 * 24, 24);
            wmma::load_matrix_sync(b_lo, Bs + BPL + nt * 16 * 24, 24);
            wmma::mma_sync(acc[nt], a_hi, b_hi, acc[nt]);
            wmma::mma_sync(acc[nt], a_hi, b_lo, acc[nt]);
            wmma::mma_sync(acc[nt], a_lo, b_hi, acc[nt]);
        }
    }
    __syncthreads();

    // epilogue via per-warp 16x20 patch
    float* pp = patch + warp * (16 * 20);
    int rr = lane >> 1;
    int c0 = (lane & 1) * 8;
    int mrow = tile * 128 + warp * 16 + rr;
    bool valid = mrow < NN;
    float hasb = 0.f;
    if (MODE == 0) hasb = (valid && g_inv[mrow] > 0.f) ? 1.f : 0.f;

    for (int nt = 0; nt < NT; nt++) {
        wmma::store_matrix_sync(pp, acc[nt], 20, wmma::mem_row_major);
        __syncwarp();
        if (MODE == 0) {
#pragma unroll
            for (int i = 0; i < 8; i++) {
                int j = nt * 16 + c0 + i;
                float v = valid ? (pp[rr * 20 + c0 + i] + hasb * bias_s[j]) : 0.f;
                float e = (v > 0.f) ? v : expm1f(v);
                __nv_bfloat16 hi, lo; bfsplit(e, hi, lo);
                size_t off = (size_t)mrow * KP + j;
                g_Actx[off] = hi;
                g_Actx[AGPL + off] = lo;
            }
        } else if (valid) {
            float* gp = g_gates + (size_t)y * NN * GG + (size_t)mrow * GG;
#pragma unroll
            for (int i = 0; i < 8; i++) {
                int j = nt * 16 + c0 + i;
                if (j < GG) gp[j] = pp[rr * 20 + c0 + i] + bias_s[j];
            }
        }
        __syncwarp();
    }
}

// ---------------- k_gate: elementwise GRU combine + relu ----------------------
__global__ void k_gate(float* __restrict__ out) {
    int idx = blockIdx.x * blockDim.x + threadIdx.x;
    if (idx >= NN * GG) return;
    const size_t S = (size_t)NN * GG;
    float ir = g_gates[idx],         iz = g_gates[S + idx],     inn = g_gates[2 * S + idx];
    float hr = g_gates[3 * S + idx], hz = g_gates[4 * S + idx], hn  = g_gates[5 * S + idx];
    float r = sigm(ir + hr);
    float z = sigm(iz + hz);
    float n = tanhf(inn + r * hn);
    float hv = g_hv[idx];
    float h = (1.f - z) * n + z * hv;
    out[idx] = fmaxf(h, 0.f);
}

// ---------------- launch -------------------------------------------------------
extern "C" void kernel_launch(void* const* d_in, const int* in_sizes, int n_in,
                              void* d_out, int out_size) {
    const float* nf  = (const float*)d_in[0];
    const float* ef  = (const float*)d_in[1];
    const int*   src = (const int*)d_in[2];
    const int*   dst = (const int*)d_in[3];
    const float* Wn  = (const float*)d_in[4];
    const float* bn  = (const float*)d_in[5];
    const float* We1 = (const float*)d_in[6];
    const float* be1 = (const float*)d_in[7];
    const float* We2 = (const float*)d_in[8];
    const float* be2 = (const float*)d_in[9];
    const float* Wet = (const float*)d_in[10];
    const float* bet = (const float*)d_in[11];
    const float* Wih = (const float*)d_in[12];
    const float* bih = (const float*)d_in[13];
    const float* Whh = (const float*)d_in[14];
    const float* bhh = (const float*)d_in[15];
    float* out = (float*)d_out;

    cudaFuncSetAttribute(k_nodeproj, cudaFuncAttributeMaxDynamicSharedMemorySize, NP_SMEM * 4);
    cudaFuncSetAttribute(k_edge1,    cudaFuncAttributeMaxDynamicSharedMemorySize, E_SMEM * 4);

    k_init<<<(NN * GG + 255) / 256, 256>>>();
    k_packW<<<(7 * KP * KP + 255) / 256, 256>>>(Wet, Wih, Whh);
    k_nodeproj<<<MPAD / 32, 256, NP_SMEM * 4>>>(nf, Wn, bn, We2, We1);
    k_edge1<<<1184, 256, E_SMEM * 4>>>(ef, src, dst, We1, be1, We2, be2);
    k_inv<<<(NN + 255) / 256, 256>>>();
    k_packS<<<(int)(((size_t)MPAD * KP + 255) / 256), 256>>>();
    k_wmma<0><<<NTILE, 256>>>(bet, nullptr);
    k_wmma<1><<<dim3(NTILE, 6), 256>>>(bih, bhh);
    k_gate<<<(NN * GG + 255) / 256, 256>>>(out);
}